// round 15
// baseline (speedup 1.0000x reference)
#include <cuda_runtime.h>
#include <stdint.h>

// YOLACT-550 Fast-NMS, GB300 sm_103a — round 14
// R13 base (64.5us) with ONE functional change: suppression processes 64
// pairs per chunk (2 boxes per lane, overlapped LDS) -> half the serial
// chunks / ballots on the critical warp. Plus a free trim: dst padded only
// to CLEAN on the bucket path (nothing beyond CLEAN is read there).

#define NB   16
#define NC   80
#define NN   19248
#define NV4  4812            // NN/4
#define KTOP 200
#define CAP  512
#define NT   256
#define NWARP (NT/32)

#define NBUCK  1280          // used buckets ~1088 at T=0.98337 (lambda~0.29)
#define BSHIFT 8
#define BPT    (NBUCK/NT)    // 5 buckets per thread
#define CLEAN  208           // cleanup window (KTOP + max displacement 8)

__device__ __forceinline__ unsigned long long mk_key(uint32_t v, uint32_t idx) {
    // descending value, ascending index on ties (matches jax.lax.top_k)
    return ((unsigned long long)v << 32) | (unsigned long long)(0xFFFFFFFFu - idx);
}

__device__ __forceinline__ int bucket_of(uint32_t valbits) {
    int d = (int)(0x3F800000u - valbits);        // smaller delta = larger value
    d = (d < 0) ? 0 : d;
    int b = d >> BSHIFT;
    return (b > NBUCK - 1) ? (NBUCK - 1) : b;    // clamp keeps monotonicity
}

__global__ __launch_bounds__(NT, 6)
void fastnms_kernel(const float* __restrict__ boxes_raw,
                    const float* __restrict__ scores,
                    float* __restrict__ out)
{
    __shared__ unsigned long long cand[CAP];     // collected keys; also stage
    __shared__ unsigned long long dst[CAP];      // sorted keys (bucket path)
    __shared__ uint32_t counts[NBUCK];
    __shared__ float4   sboxv[KTOP];
    __shared__ float    sar[KTOP];
    __shared__ uint32_t keepf[KTOP];
    __shared__ uint32_t red[32];
    __shared__ int scnt;

    const int tid  = threadIdx.x;
    const int lane = tid & 31;
    const int wid  = tid >> 5;
    const int bc   = blockIdx.x;                 // b*NC + c
    const int b    = bc / NC;

    const uint4* srow = reinterpret_cast<const uint4*>(scores) + (size_t)bc * NV4;

    // ---------------- 1. Compare-only streaming scan at statistical threshold --
    // Scores are non-negative floats: raw-bit unsigned compare == float compare.
    uint32_t T = __float_as_uint(0.98337f);      // E[count] ~= 320, sigma ~= 18

    if (tid == 0) scnt = 0;
    #pragma unroll
    for (int t = 0; t < BPT; ++t) counts[tid + t * NT] = 0u;   // zero buckets
    __syncthreads();

    #pragma unroll 4
    for (int i = tid; i < NV4; i += NT) {
        uint4 v = __ldcs(srow + i);              // streaming: single-use data
        if (max(max(v.x, v.y), max(v.z, v.w)) >= T) {   // 3 IMNMX + 1 cmp, rare
            uint32_t vals[4] = {v.x, v.y, v.z, v.w};
            #pragma unroll
            for (int j = 0; j < 4; ++j) {
                if (vals[j] >= T) {
                    int p = atomicAdd(&scnt, 1);
                    if (p < CAP) cand[p] = mk_key(vals[j], (uint32_t)(4 * i + j));
                }
            }
        }
    }
    __syncthreads();
    int M = scnt;

    // ---------------- 2. Exact fallback (statistically never taken) ------------
    if (M < KTOP || M > CAP) {
        uint32_t mymax = 0u;
        for (int i = tid; i < NV4; i += NT) {
            uint4 v = srow[i];
            mymax = max(mymax, max(max(v.x, v.y), max(v.z, v.w)));
        }
        #pragma unroll
        for (int o = 16; o; o >>= 1)
            mymax = max(mymax, __shfl_xor_sync(0xFFFFFFFFu, mymax, o));
        if (lane == 0) red[wid] = mymax;
        __syncthreads();
        if (tid == 0) {
            uint32_t mm = red[0];
            for (int w = 1; w < NWARP; ++w) mm = max(mm, red[w]);
            red[16] = mm;
        }
        __syncthreads();

        uint32_t lo = 0u, hi = red[16];
        T = 0u;
        int bestGe = NN;
        for (int it = 0; it < 34 && lo <= hi; ++it) {
            uint32_t t = lo + ((hi - lo) >> 1);
            int c = 0;
            for (int i = tid; i < NV4; i += NT) {
                uint4 v = srow[i];
                c += (v.x >= t) + (v.y >= t) + (v.z >= t) + (v.w >= t);
            }
            #pragma unroll
            for (int o = 16; o; o >>= 1) c += __shfl_down_sync(0xFFFFFFFFu, c, o);
            __syncthreads();
            if (lane == 0) red[wid] = (uint32_t)c;
            __syncthreads();
            if (tid == 0) {
                int s = 0;
                for (int w = 0; w < NWARP; ++w) s += (int)red[w];
                red[17] = (uint32_t)s;
            }
            __syncthreads();
            int ge = (int)red[17];
            if (ge >= KTOP) {
                if (ge < bestGe) { bestGe = ge; T = t; }
                if (ge <= CAP) break;
                lo = t + 1;
            } else {
                if (t == 0) break;
                hi = t - 1;
            }
        }

        __syncthreads();
        if (tid == 0) scnt = 0;
        __syncthreads();
        for (int i = tid; i < NV4; i += NT) {
            uint4 v = srow[i];
            if (max(max(v.x, v.y), max(v.z, v.w)) >= T) {
                uint32_t vals[4] = {v.x, v.y, v.z, v.w};
                #pragma unroll
                for (int j = 0; j < 4; ++j) {
                    if (vals[j] >= T) {
                        int p = atomicAdd(&scnt, 1);
                        if (p < CAP) cand[p] = mk_key(vals[j], (uint32_t)(4 * i + j));
                    }
                }
            }
        }
        __syncthreads();
        M = min(scnt, CAP);
    }

    // ---------------- 3. Counting sort (exact, guarded) ------------------------
    // 3a. count
    for (int i = tid; i < M; i += NT) {
        uint32_t v = (uint32_t)(cand[i] >> 32);
        atomicAdd(&counts[bucket_of(v)], 1u);
    }
    __syncthreads();

    // 3b. per-thread chunk sum + max; block max guard
    const int basek = tid * BPT;
    uint32_t csum = 0u, cmax = 0u;
    #pragma unroll
    for (int t = 0; t < BPT; ++t) {
        uint32_t c = counts[basek + t];
        csum += c;
        cmax = max(cmax, c);
    }
    #pragma unroll
    for (int o = 16; o; o >>= 1)
        cmax = max(cmax, __shfl_xor_sync(0xFFFFFFFFu, cmax, o));
    if (lane == 0) red[wid] = cmax;
    __syncthreads();
    if (tid == 0) {
        uint32_t mm = red[0];
        for (int w = 1; w < NWARP; ++w) mm = max(mm, red[w]);
        red[16] = mm;
    }
    __syncthreads();
    const bool bucket_ok = (red[16] <= 8u);
    __syncthreads();

    unsigned long long* sorted;
    if (bucket_ok) {
        // 3c. exclusive block scan of per-thread sums
        uint32_t incl = csum;
        #pragma unroll
        for (int o = 1; o < 32; o <<= 1) {
            uint32_t t = __shfl_up_sync(0xFFFFFFFFu, incl, o);
            if (lane >= o) incl += t;
        }
        uint32_t wex = incl - csum;              // exclusive within warp
        if (lane == 31) red[8 + wid] = incl;     // warp totals
        __syncthreads();
        if (tid == 0) {
            uint32_t run = 0u;
            for (int w = 0; w < NWARP; ++w) {
                uint32_t t = red[8 + w];
                red[8 + w] = run;
                run += t;
            }
        }
        __syncthreads();
        uint32_t tex = red[8 + wid] + wex;       // thread's exclusive base

        // 3d. write back bucket start offsets (counts -> fill pointers)
        uint32_t run = tex;
        #pragma unroll
        for (int t = 0; t < BPT; ++t) {
            uint32_t c = counts[basek + t];
            counts[basek + t] = run;
            run += c;
        }
        __syncthreads();

        // 3e. stable scatter (pos < M always: fill pointers sum to M)
        for (int i = tid; i < M; i += NT) {
            unsigned long long key = cand[i];
            int bkt = bucket_of((uint32_t)(key >> 32));
            uint32_t pos = atomicAdd(&counts[bkt], 1u);
            dst[pos] = key;
        }
        // pad only the read window: sorted[<KTOP] and cleanup[<CLEAN]
        for (int i = M + tid; i < CLEAN; i += NT) dst[i] = 0ull;
        __syncthreads();

        // 3f. 8 odd-even cleanup passes over [0, CLEAN): disorder confined to
        // <=8-wide buckets; buckets touching [0,KTOP) lie inside [0,CLEAN).
        #pragma unroll 1
        for (int p = 0; p < 8; ++p) {
            int l = 2 * tid + (p & 1);
            int r = l + 1;
            if (r < CLEAN) {
                unsigned long long a = dst[l];
                unsigned long long c2 = dst[r];
                if (a < c2) { dst[l] = c2; dst[r] = a; }
            }
            __syncthreads();
        }
        sorted = dst;
    } else {
        // guarded fallback: full smem bitonic (rare/never)
        for (int i = M + tid; i < CAP; i += NT) cand[i] = 0ull;
        __syncthreads();
        #pragma unroll 1
        for (int k = 2; k <= CAP; k <<= 1) {
            #pragma unroll 1
            for (int j = k >> 1; j > 0; j >>= 1) {
                int i   = 2 * tid - (tid & (j - 1));
                int ixj = i + j;
                unsigned long long a  = cand[i];
                unsigned long long c2 = cand[ixj];
                bool desc = ((i & k) == 0);
                if ((a < c2) == desc) { cand[i] = c2; cand[ixj] = a; }
                __syncthreads();
            }
        }
        sorted = cand;
    }

    // ---------------- 4. Gather + decode boxes ---------------------------------
    float x1 = 0.f, y1v = 0.f, x2 = 0.f, y2v = 0.f, sc = 0.f;
    if (tid < KTOP) {
        unsigned long long key = sorted[tid];
        uint32_t idx = 0xFFFFFFFFu - (uint32_t)(key & 0xFFFFFFFFull);
        sc = __uint_as_float((uint32_t)(key >> 32));
        float4 rb = __ldg(reinterpret_cast<const float4*>(boxes_raw) + (size_t)b * NN + idx);
        float w  = rb.z * 0.5f + 1e-2f;
        float h  = rb.w * 0.5f + 1e-2f;
        float hw = 0.5f * w, hh = 0.5f * h;
        x1  = rb.x - hw;  x2  = rb.x + hw;
        y1v = rb.y - hh;  y2v = rb.y + hh;
        sboxv[tid] = make_float4(x1, y1v, x2, y2v);
        sar[tid]   = (x2 - x1) * (y2v - y1v);    // area from corners (match ref)
    }
    __syncthreads();

    // ---------------- 5. Suppression: 64-wide chunks + early exit --------------
    // iou <= 0.5  <=>  2*inter <= union  <=>  3*inter <= area_i + area_j
    for (int j = wid; j < KTOP; j += NWARP) {
        float4 bj = sboxv[j];
        float  aj = sar[j];
        bool sup = false;
        for (int i0 = 0; i0 < j; i0 += 64) {
            int i1 = i0 + lane;
            int i2 = i1 + 32;
            bool s = false;
            if (i1 < j) {                        // both LDS issued back-to-back
                float4 b1 = sboxv[i1];
                float iw1 = fminf(bj.z, b1.z) - fmaxf(bj.x, b1.x);
                float ih1 = fminf(bj.w, b1.w) - fmaxf(bj.y, b1.y);
                iw1 = fmaxf(iw1, 0.f);
                ih1 = fmaxf(ih1, 0.f);
                s = (3.0f * (iw1 * ih1) > aj + sar[i1]);
            }
            if (i2 < j) {
                float4 b2 = sboxv[i2];
                float iw2 = fminf(bj.z, b2.z) - fmaxf(bj.x, b2.x);
                float ih2 = fminf(bj.w, b2.w) - fmaxf(bj.y, b2.y);
                iw2 = fmaxf(iw2, 0.f);
                ih2 = fmaxf(ih2, 0.f);
                s = s || (3.0f * (iw2 * ih2) > aj + sar[i2]);
            }
            if (__any_sync(0xFFFFFFFFu, s)) { sup = true; break; }
        }
        if (lane == 0) keepf[j] = sup ? 0u : 1u;
    }
    __syncthreads();                             // guards cand reuse below

    // ---------------- 6. Stage + coalesced output write ------------------------
    float* stage = reinterpret_cast<float*>(cand);   // 4KB >= 200*5*4B
    if (tid < KTOP) {
        float osc = (keepf[tid] && sc > 0.05f) ? sc : 0.f;
        stage[tid * 5 + 0] = osc;
        stage[tid * 5 + 1] = x1;
        stage[tid * 5 + 2] = y1v;
        stage[tid * 5 + 3] = x2;
        stage[tid * 5 + 4] = y2v;
    }
    __syncthreads();

    {   // 1000 floats = 250 uint4 per row
        uint4* dstg = reinterpret_cast<uint4*>(out + (size_t)bc * (KTOP * 5));
        const uint4* srcg = reinterpret_cast<const uint4*>(stage);
        if (tid < 250) dstg[tid] = srcg[tid];
    }
}

extern "C" void kernel_launch(void* const* d_in, const int* in_sizes, int n_in,
                              void* d_out, int out_size)
{
    const float* boxes  = (const float*)d_in[0];
    const float* scores = (const float*)d_in[1];
    if (n_in >= 2 && in_sizes[0] > in_sizes[1]) {   // defensive order check
        boxes  = (const float*)d_in[1];
        scores = (const float*)d_in[0];
    }
    (void)out_size;
    fastnms_kernel<<<NB * NC, NT>>>(boxes, scores, (float*)d_out);
}

// round 16
// speedup vs baseline: 1.0960x; 1.0960x over previous
#include <cuda_runtime.h>
#include <stdint.h>

// YOLACT-550 Fast-NMS, GB300 sm_103a — round 15
// R13 base (64.5us; R14's 64-wide suppression chunk regressed and is
// reverted). Three exact trims:
//   (1) adaptive odd-even cleanup: min(cmax+1, 8) passes (cmax = bucket max)
//   (2) merged guard-max + prefix-sum block reduction (2 fewer barriers)
//   (3) dst padded only to CLEAN on the bucket path (dead stores removed)

#define NB   16
#define NC   80
#define NN   19248
#define NV4  4812            // NN/4
#define KTOP 200
#define CAP  512
#define NT   256
#define NWARP (NT/32)

#define NBUCK  1280          // used buckets ~1088 at T=0.98337 (lambda~0.29)
#define BSHIFT 8
#define BPT    (NBUCK/NT)    // 5 buckets per thread
#define CLEAN  208           // cleanup window (KTOP + max displacement 8)

__device__ __forceinline__ unsigned long long mk_key(uint32_t v, uint32_t idx) {
    // descending value, ascending index on ties (matches jax.lax.top_k)
    return ((unsigned long long)v << 32) | (unsigned long long)(0xFFFFFFFFu - idx);
}

__device__ __forceinline__ int bucket_of(uint32_t valbits) {
    int d = (int)(0x3F800000u - valbits);        // smaller delta = larger value
    d = (d < 0) ? 0 : d;
    int b = d >> BSHIFT;
    return (b > NBUCK - 1) ? (NBUCK - 1) : b;    // clamp keeps monotonicity
}

__global__ __launch_bounds__(NT, 6)
void fastnms_kernel(const float* __restrict__ boxes_raw,
                    const float* __restrict__ scores,
                    float* __restrict__ out)
{
    __shared__ unsigned long long cand[CAP];     // collected keys; also stage
    __shared__ unsigned long long dst[CAP];      // sorted keys (bucket path)
    __shared__ uint32_t counts[NBUCK];
    __shared__ float4   sboxv[KTOP];
    __shared__ float    sar[KTOP];
    __shared__ uint32_t keepf[KTOP];
    __shared__ uint32_t red[32];
    __shared__ int scnt;

    const int tid  = threadIdx.x;
    const int lane = tid & 31;
    const int wid  = tid >> 5;
    const int bc   = blockIdx.x;                 // b*NC + c
    const int b    = bc / NC;

    const uint4* srow = reinterpret_cast<const uint4*>(scores) + (size_t)bc * NV4;

    // ---------------- 1. Compare-only streaming scan at statistical threshold --
    // Scores are non-negative floats: raw-bit unsigned compare == float compare.
    uint32_t T = __float_as_uint(0.98337f);      // E[count] ~= 320, sigma ~= 18

    if (tid == 0) scnt = 0;
    #pragma unroll
    for (int t = 0; t < BPT; ++t) counts[tid + t * NT] = 0u;   // zero buckets
    __syncthreads();

    #pragma unroll 4
    for (int i = tid; i < NV4; i += NT) {
        uint4 v = __ldcs(srow + i);              // streaming: single-use data
        if (max(max(v.x, v.y), max(v.z, v.w)) >= T) {   // 3 IMNMX + 1 cmp, rare
            uint32_t vals[4] = {v.x, v.y, v.z, v.w};
            #pragma unroll
            for (int j = 0; j < 4; ++j) {
                if (vals[j] >= T) {
                    int p = atomicAdd(&scnt, 1);
                    if (p < CAP) cand[p] = mk_key(vals[j], (uint32_t)(4 * i + j));
                }
            }
        }
    }
    __syncthreads();
    int M = scnt;

    // ---------------- 2. Exact fallback (statistically never taken) ------------
    if (M < KTOP || M > CAP) {
        uint32_t mymax = 0u;
        for (int i = tid; i < NV4; i += NT) {
            uint4 v = srow[i];
            mymax = max(mymax, max(max(v.x, v.y), max(v.z, v.w)));
        }
        #pragma unroll
        for (int o = 16; o; o >>= 1)
            mymax = max(mymax, __shfl_xor_sync(0xFFFFFFFFu, mymax, o));
        if (lane == 0) red[wid] = mymax;
        __syncthreads();
        if (tid == 0) {
            uint32_t mm = red[0];
            for (int w = 1; w < NWARP; ++w) mm = max(mm, red[w]);
            red[16] = mm;
        }
        __syncthreads();

        uint32_t lo = 0u, hi = red[16];
        T = 0u;
        int bestGe = NN;
        for (int it = 0; it < 34 && lo <= hi; ++it) {
            uint32_t t = lo + ((hi - lo) >> 1);
            int c = 0;
            for (int i = tid; i < NV4; i += NT) {
                uint4 v = srow[i];
                c += (v.x >= t) + (v.y >= t) + (v.z >= t) + (v.w >= t);
            }
            #pragma unroll
            for (int o = 16; o; o >>= 1) c += __shfl_down_sync(0xFFFFFFFFu, c, o);
            __syncthreads();
            if (lane == 0) red[wid] = (uint32_t)c;
            __syncthreads();
            if (tid == 0) {
                int s = 0;
                for (int w = 0; w < NWARP; ++w) s += (int)red[w];
                red[17] = (uint32_t)s;
            }
            __syncthreads();
            int ge = (int)red[17];
            if (ge >= KTOP) {
                if (ge < bestGe) { bestGe = ge; T = t; }
                if (ge <= CAP) break;
                lo = t + 1;
            } else {
                if (t == 0) break;
                hi = t - 1;
            }
        }

        __syncthreads();
        if (tid == 0) scnt = 0;
        __syncthreads();
        for (int i = tid; i < NV4; i += NT) {
            uint4 v = srow[i];
            if (max(max(v.x, v.y), max(v.z, v.w)) >= T) {
                uint32_t vals[4] = {v.x, v.y, v.z, v.w};
                #pragma unroll
                for (int j = 0; j < 4; ++j) {
                    if (vals[j] >= T) {
                        int p = atomicAdd(&scnt, 1);
                        if (p < CAP) cand[p] = mk_key(vals[j], (uint32_t)(4 * i + j));
                    }
                }
            }
        }
        __syncthreads();
        M = min(scnt, CAP);
    }

    // ---------------- 3. Counting sort (exact, guarded) ------------------------
    // 3a. count
    for (int i = tid; i < M; i += NT) {
        uint32_t v = (uint32_t)(cand[i] >> 32);
        atomicAdd(&counts[bucket_of(v)], 1u);
    }
    __syncthreads();

    // 3b. merged reduction: per-thread chunk sum + max; warp scan of sums AND
    //     warp max in one pass; single tid0 combine (guard + warp offsets)
    const int basek = tid * BPT;
    uint32_t csum = 0u, cmax = 0u;
    #pragma unroll
    for (int t = 0; t < BPT; ++t) {
        uint32_t c = counts[basek + t];
        csum += c;
        cmax = max(cmax, c);
    }
    uint32_t incl = csum;
    #pragma unroll
    for (int o = 1; o < 32; o <<= 1) {
        uint32_t t = __shfl_up_sync(0xFFFFFFFFu, incl, o);
        if (lane >= o) incl += t;
    }
    #pragma unroll
    for (int o = 16; o; o >>= 1)
        cmax = max(cmax, __shfl_xor_sync(0xFFFFFFFFu, cmax, o));
    uint32_t wex = incl - csum;                  // exclusive within warp
    if (lane == 31) red[8 + wid] = incl;         // warp total sums
    if (lane == 0)  red[wid] = cmax;             // warp maxes
    __syncthreads();
    if (tid == 0) {
        uint32_t mm = red[0];
        for (int w = 1; w < NWARP; ++w) mm = max(mm, red[w]);
        red[16] = mm;                            // block max (guard)
        uint32_t run = 0u;
        for (int w = 0; w < NWARP; ++w) {
            uint32_t t = red[8 + w];
            red[8 + w] = run;
            run += t;
        }
    }
    __syncthreads();
    const int  bmax = (int)red[16];
    const bool bucket_ok = (bmax <= 8);

    unsigned long long* sorted;
    if (bucket_ok) {
        uint32_t tex = red[8 + wid] + wex;       // thread's exclusive base

        // 3d. write back bucket start offsets (counts -> fill pointers)
        uint32_t run = tex;
        #pragma unroll
        for (int t = 0; t < BPT; ++t) {
            uint32_t c = counts[basek + t];
            counts[basek + t] = run;
            run += c;
        }
        __syncthreads();

        // 3e. stable scatter (pos < M always: fill pointers sum to M)
        for (int i = tid; i < M; i += NT) {
            unsigned long long key = cand[i];
            int bkt = bucket_of((uint32_t)(key >> 32));
            uint32_t pos = atomicAdd(&counts[bkt], 1u);
            dst[pos] = key;
        }
        // pad only the read window: sorted[<KTOP] and cleanup[<CLEAN]
        for (int i = M + tid; i < CLEAN; i += NT) dst[i] = 0ull;
        __syncthreads();

        // 3f. adaptive odd-even cleanup over [0, CLEAN): a within-bucket block
        // of size s (s <= bmax) sorts in <= s+1 passes at either parity start.
        const int passes = min(bmax + 1, 8);
        #pragma unroll 1
        for (int p = 0; p < passes; ++p) {
            int l = 2 * tid + (p & 1);
            int r = l + 1;
            if (r < CLEAN) {
                unsigned long long a = dst[l];
                unsigned long long c2 = dst[r];
                if (a < c2) { dst[l] = c2; dst[r] = a; }
            }
            __syncthreads();
        }
        sorted = dst;
    } else {
        // guarded fallback: full smem bitonic (rare/never)
        for (int i = M + tid; i < CAP; i += NT) cand[i] = 0ull;
        __syncthreads();
        #pragma unroll 1
        for (int k = 2; k <= CAP; k <<= 1) {
            #pragma unroll 1
            for (int j = k >> 1; j > 0; j >>= 1) {
                int i   = 2 * tid - (tid & (j - 1));
                int ixj = i + j;
                unsigned long long a  = cand[i];
                unsigned long long c2 = cand[ixj];
                bool desc = ((i & k) == 0);
                if ((a < c2) == desc) { cand[i] = c2; cand[ixj] = a; }
                __syncthreads();
            }
        }
        sorted = cand;
    }

    // ---------------- 4. Gather + decode boxes ---------------------------------
    float x1 = 0.f, y1v = 0.f, x2 = 0.f, y2v = 0.f, sc = 0.f;
    if (tid < KTOP) {
        unsigned long long key = sorted[tid];
        uint32_t idx = 0xFFFFFFFFu - (uint32_t)(key & 0xFFFFFFFFull);
        sc = __uint_as_float((uint32_t)(key >> 32));
        float4 rb = __ldg(reinterpret_cast<const float4*>(boxes_raw) + (size_t)b * NN + idx);
        float w  = rb.z * 0.5f + 1e-2f;
        float h  = rb.w * 0.5f + 1e-2f;
        float hw = 0.5f * w, hh = 0.5f * h;
        x1  = rb.x - hw;  x2  = rb.x + hw;
        y1v = rb.y - hh;  y2v = rb.y + hh;
        sboxv[tid] = make_float4(x1, y1v, x2, y2v);
        sar[tid]   = (x2 - x1) * (y2v - y1v);    // area from corners (match ref)
    }
    __syncthreads();

    // ---------------- 5. Suppression: 32-wide chunks + early exit --------------
    // iou <= 0.5  <=>  2*inter <= union  <=>  3*inter <= area_i + area_j
    for (int j = wid; j < KTOP; j += NWARP) {
        float4 bj = sboxv[j];
        float  aj = sar[j];
        bool sup = false;
        for (int i0 = 0; i0 < j; i0 += 32) {
            int i = i0 + lane;
            bool s = false;
            if (i < j) {
                float4 bi = sboxv[i];
                float iw = fminf(bj.z, bi.z) - fmaxf(bj.x, bi.x);
                float ih = fminf(bj.w, bi.w) - fmaxf(bj.y, bi.y);
                iw = fmaxf(iw, 0.f);
                ih = fmaxf(ih, 0.f);
                s = (3.0f * (iw * ih) > aj + sar[i]);
            }
            if (__any_sync(0xFFFFFFFFu, s)) { sup = true; break; }
        }
        if (lane == 0) keepf[j] = sup ? 0u : 1u;
    }
    __syncthreads();                             // guards cand reuse below

    // ---------------- 6. Stage + coalesced output write ------------------------
    float* stage = reinterpret_cast<float*>(cand);   // 4KB >= 200*5*4B
    if (tid < KTOP) {
        float osc = (keepf[tid] && sc > 0.05f) ? sc : 0.f;
        stage[tid * 5 + 0] = osc;
        stage[tid * 5 + 1] = x1;
        stage[tid * 5 + 2] = y1v;
        stage[tid * 5 + 3] = x2;
        stage[tid * 5 + 4] = y2v;
    }
    __syncthreads();

    {   // 1000 floats = 250 uint4 per row
        uint4* dstg = reinterpret_cast<uint4*>(out + (size_t)bc * (KTOP * 5));
        const uint4* srcg = reinterpret_cast<const uint4*>(stage);
        if (tid < 250) dstg[tid] = srcg[tid];
    }
}

extern "C" void kernel_launch(void* const* d_in, const int* in_sizes, int n_in,
                              void* d_out, int out_size)
{
    const float* boxes  = (const float*)d_in[0];
    const float* scores = (const float*)d_in[1];
    if (n_in >= 2 && in_sizes[0] > in_sizes[1]) {   // defensive order check
        boxes  = (const float*)d_in[1];
        scores = (const float*)d_in[0];
    }
    (void)out_size;
    fastnms_kernel<<<NB * NC, NT>>>(boxes, scores, (float*)d_out);
}